// round 7
// baseline (speedup 1.0000x reference)
#include <cuda_runtime.h>
#include <math.h>
#include <stdint.h>

// Problem dims
#define BB    128
#define NNA   256
#define DD    256
#define MSGD  64
#define CDD   32
#define KKK   8
#define H1D   128
#define H2D   256
#define BNT   (BB*NNA)   // 32768

// -------- device scratch --------
__device__ float g_W2p[H1D*MSGD];
__device__ float g_b2p[MSGD];
__device__ float g_obst[(long)BNT*DD];      // tf32-rounded obs
__device__ float g_W1t [DD*H1D];
__device__ float g_Wbilt[DD*DD];
__device__ float g_Wr1t[(DD+MSGD)*H2D];
__device__ float g_Wr2t[H2D*DD];
__device__ float g_h   [(long)BNT*H1D];
__device__ float g_msgs[(long)BNT*MSGD];
__device__ float g_tmp [(long)BNT*DD];
__device__ float g_agg [(long)BNT*MSGD];
__device__ float g_r   [(long)BNT*H2D];

// ============================================================
// helpers
// ============================================================
__device__ __forceinline__ float to_tf32(float x) {
    uint32_t u;
    asm("cvt.rna.tf32.f32 %0, %1;" : "=r"(u) : "f"(x));
    return __uint_as_float(u);
}

__device__ __forceinline__ void mma8(float* c, const uint32_t* a, const uint32_t* b) {
    asm volatile(
        "mma.sync.aligned.m16n8k8.row.col.f32.tf32.tf32.f32 "
        "{%0,%1,%2,%3}, {%4,%5,%6,%7}, {%8,%9}, {%0,%1,%2,%3};"
        : "+f"(c[0]), "+f"(c[1]), "+f"(c[2]), "+f"(c[3])
        : "r"(a[0]), "r"(a[1]), "r"(a[2]), "r"(a[3]), "r"(b[0]), "r"(b[1]));
}

__device__ __forceinline__ void cp16(void* smem_dst, const void* gmem_src) {
    uint32_t s = (uint32_t)__cvta_generic_to_shared(smem_dst);
    asm volatile("cp.async.cg.shared.global [%0], [%1], 16;" :: "r"(s), "l"(gmem_src));
}
#define CP_COMMIT() asm volatile("cp.async.commit_group;")
#define CP_WAIT0()  asm volatile("cp.async.wait_group 0;")
#define CP_WAIT1()  asm volatile("cp.async.wait_group 1;")

// ============================================================
// conversion kernels (fp32 -> tf32-rounded fp32)
// ============================================================
__global__ void cvt_kernel(const float* __restrict__ src, float* __restrict__ dst, int n4) {
    int i = blockIdx.x * blockDim.x + threadIdx.x;
    if (i < n4) {
        float4 v = ((const float4*)src)[i];
        ((float4*)dst)[i] = make_float4(to_tf32(v.x), to_tf32(v.y), to_tf32(v.z), to_tf32(v.w));
    }
}

__global__ void cvt_weights(const float* __restrict__ W1, const float* __restrict__ Wbil,
                            const float* __restrict__ Wr1, const float* __restrict__ Wr2) {
    int i = blockIdx.x * blockDim.x + threadIdx.x;
    if (i < DD*H1D/4) {
        float4 v = ((const float4*)W1)[i];
        ((float4*)g_W1t)[i] = make_float4(to_tf32(v.x), to_tf32(v.y), to_tf32(v.z), to_tf32(v.w));
    }
    if (i < DD*DD/4) {
        float4 v = ((const float4*)Wbil)[i];
        ((float4*)g_Wbilt)[i] = make_float4(to_tf32(v.x), to_tf32(v.y), to_tf32(v.z), to_tf32(v.w));
    }
    if (i < (DD+MSGD)*H2D/4) {
        float4 v = ((const float4*)Wr1)[i];
        ((float4*)g_Wr1t)[i] = make_float4(to_tf32(v.x), to_tf32(v.y), to_tf32(v.z), to_tf32(v.w));
    }
    if (i < H2D*DD/4) {
        float4 v = ((const float4*)Wr2)[i];
        ((float4*)g_Wr2t)[i] = make_float4(to_tf32(v.x), to_tf32(v.y), to_tf32(v.z), to_tf32(v.w));
    }
}

// ============================================================
// 0) Compose W2' = W2@Wc@Wd (tf32-rounded), b2' composed (fp32)
// ============================================================
__global__ void prep_kernel(const float* __restrict__ W2, const float* __restrict__ b2,
                            const float* __restrict__ Wc, const float* __restrict__ bc,
                            const float* __restrict__ Wd, const float* __restrict__ bd) {
    __shared__ float bbuf[CDD];
    int t = threadIdx.x; // 128 threads
    float T[CDD];
    #pragma unroll
    for (int c = 0; c < CDD; c++) T[c] = 0.f;
    for (int m = 0; m < MSGD; m++) {
        float w = W2[t*MSGD + m];
        #pragma unroll
        for (int c = 0; c < CDD; c++) T[c] += w * Wc[m*CDD + c];
    }
    for (int mm = 0; mm < MSGD; mm++) {
        float acc = 0.f;
        #pragma unroll
        for (int c = 0; c < CDD; c++) acc += T[c] * Wd[c*MSGD + mm];
        g_W2p[t*MSGD + mm] = to_tf32(acc);
    }
    if (t < CDD) {
        float acc = bc[t];
        for (int m = 0; m < MSGD; m++) acc += b2[m] * Wc[m*CDD + t];
        bbuf[t] = acc;
    }
    __syncthreads();
    if (t < MSGD) {
        float acc = bd[t];
        #pragma unroll
        for (int c = 0; c < CDD; c++) acc += bbuf[c] * Wd[c*MSGD + t];
        g_b2p[t] = acc;
    }
}

// ============================================================
// tf32 MMA GEMM (NN), cp.async 3-stage pipeline, dynamic smem.
//   A row-major (lda), virtual concat with A2 at column splitK
//   B row-major (ldb); all operands tf32-pre-rounded.
// ============================================================
#define BM  128
#define BK  16
#define AP  20   // A smem pitch ([m][k])

template<int BNt, int WM, int WN, bool RELU, bool BIASV, bool CVTOUT>
__global__ __launch_bounds__(256, 2) void mma_nn(
    const float* __restrict__ A,  int lda,
    const float* __restrict__ A2, int lda2, int splitK,
    const float* __restrict__ Bw, int ldb,
    float* __restrict__ C, int ldc, int Kdim,
    const float* __restrict__ bias)
{
    static_assert(WM * WN == 8, "");
    constexpr int WTM = BM / WM, WTN = BNt / WN;
    constexpr int MT = WTM / 16, NT = WTN / 8;
    constexpr int BP = BNt + 8;
    constexpr int BCNT = (BK * BNt) / (4 * 256);

    extern __shared__ float sm[];
    float* Asm = sm;                    // [3][BM][AP]
    float* Bsm = sm + 3 * BM * AP;      // [3][BK][BP]

    const int tid  = threadIdx.x;
    const int lane = tid & 31, wid = tid >> 5;
    const int lr = lane >> 2, lc = lane & 3;
    const int wm_off = (wid % WM) * WTM;
    const int wn_off = (wid / WM) * WTN;
    const long bm = (long)blockIdx.y * BM;
    const int  bn = blockIdx.x * BNt;

    const int ar = tid >> 2, akq = (tid & 3) * 4;

    auto issue = [&](int st, int k0) {
        float* As = Asm + st * BM * AP;
        float* Bs = Bsm + st * BK * BP;
        #pragma unroll
        for (int i = 0; i < 2; i++) {
            int r = ar + i * 64;
            int k = k0 + akq;
            const float* src = (k < splitK)
                ? (A  + (bm + r) * (long)lda  + k)
                : (A2 + (bm + r) * (long)lda2 + (k - splitK));
            cp16(&As[r * AP + akq], src);
        }
        #pragma unroll
        for (int i = 0; i < BCNT; i++) {
            int idx = tid + i * 256;
            int kk = idx / (BNt / 4), c4 = (idx % (BNt / 4)) * 4;
            cp16(&Bs[kk * BP + c4], Bw + (long)(k0 + kk) * ldb + bn + c4);
        }
        CP_COMMIT();
    };

    issue(0, 0);
    if (BK < Kdim) issue(1, BK);

    float acc[MT][NT][4] = {};
    int st = 0;
    for (int k0 = 0; k0 < Kdim; k0 += BK) {
        if (k0 + BK < Kdim) { CP_WAIT1(); } else { CP_WAIT0(); }
        __syncthreads();
        if (k0 + 2 * BK < Kdim) issue(st == 0 ? 2 : st - 1, k0 + 2 * BK);
        const float* As = Asm + st * BM * AP;
        const float* Bs = Bsm + st * BK * BP;
        #pragma unroll
        for (int ks = 0; ks < BK; ks += 8) {
            uint32_t af[MT][4], bf[NT][2];
            #pragma unroll
            for (int mt = 0; mt < MT; mt++) {
                int m = wm_off + mt * 16 + lr;
                af[mt][0] = __float_as_uint(As[(m    ) * AP + ks + lc    ]);
                af[mt][1] = __float_as_uint(As[(m + 8) * AP + ks + lc    ]);
                af[mt][2] = __float_as_uint(As[(m    ) * AP + ks + lc + 4]);
                af[mt][3] = __float_as_uint(As[(m + 8) * AP + ks + lc + 4]);
            }
            #pragma unroll
            for (int nt = 0; nt < NT; nt++) {
                int n = wn_off + nt * 8 + lr;
                bf[nt][0] = __float_as_uint(Bs[(ks + lc    ) * BP + n]);
                bf[nt][1] = __float_as_uint(Bs[(ks + lc + 4) * BP + n]);
            }
            #pragma unroll
            for (int mt = 0; mt < MT; mt++)
                #pragma unroll
                for (int nt = 0; nt < NT; nt++)
                    mma8(acc[mt][nt], af[mt], bf[nt]);
        }
        st = (st == 2) ? 0 : st + 1;
    }

    // epilogue
    #pragma unroll
    for (int nt = 0; nt < NT; nt++) {
        int col = bn + wn_off + nt * 8 + 2 * lc;
        float b0 = 0.f, b1 = 0.f;
        if (BIASV) { b0 = bias[col]; b1 = bias[col + 1]; }
        #pragma unroll
        for (int mt = 0; mt < MT; mt++) {
            long row = bm + wm_off + mt * 16 + lr;
            float v0 = acc[mt][nt][0] + b0, v1 = acc[mt][nt][1] + b1;
            float v2 = acc[mt][nt][2] + b0, v3 = acc[mt][nt][3] + b1;
            if (RELU) {
                v0 = fmaxf(v0, 0.f); v1 = fmaxf(v1, 0.f);
                v2 = fmaxf(v2, 0.f); v3 = fmaxf(v3, 0.f);
            }
            if (CVTOUT) {
                v0 = to_tf32(v0); v1 = to_tf32(v1);
                v2 = to_tf32(v2); v3 = to_tf32(v3);
            }
            *(float2*)(C + row * ldc + col)       = make_float2(v0, v1);
            *(float2*)(C + (row + 8) * ldc + col) = make_float2(v2, v3);
        }
    }
}

// ============================================================
// FUSED: scores tile (tmp[b] @ obst[b]^T) -> top-8 -> softmax ->
//        msg gather/aggregate -> agg.   No scores in gmem.
//   Per CTA: 64 score rows x all 256 cols. 2-stage cp.async.
//   bbil omitted: constant shift is invariant for top-k + softmax.
// ============================================================
#define FBM 64
#define FSP 260   // scores smem pitch

__global__ __launch_bounds__(256, 2) void fused_scores_topk(
    const float* __restrict__ A,   // tmp, tf32-rounded
    const float* __restrict__ Bm)  // obst
{
    // warps: WM=2 (M 2x32), WN=4 (N 4x64) -> MT=2, NT=8
    constexpr int MT = 2, NT = 8;
    extern __shared__ float sm[];
    float* Asm = sm;                    // [2][64][AP]
    float* Bsm = sm + 2 * FBM * AP;     // [2][256][AP]
    float* Ss  = sm;                    // [64][FSP]  (reused after pipeline)

    const int tid  = threadIdx.x;
    const int lane = tid & 31, wid = tid >> 5;
    const int lr = lane >> 2, lc = lane & 3;
    const int wm_off = (wid % 2) * 32;
    const int wn_off = (wid / 2) * 64;
    const int b  = blockIdx.y;
    const int bi = blockIdx.x * FBM;
    const float* Ab = A  + (long)b * NNA * DD;
    const float* Bb = Bm + (long)b * NNA * DD;

    const int akq = (tid & 3) * 4;

    auto issue = [&](int st, int k0) {
        float* As = Asm + st * FBM * AP;
        float* Bs = Bsm + st * NNA * AP;
        {
            int r = tid >> 2;   // 0..63
            cp16(&As[r * AP + akq], Ab + (long)(bi + r) * DD + k0 + akq);
        }
        #pragma unroll
        for (int i = 0; i < 4; i++) {
            int idx = tid + i * 256;
            int r = idx >> 2;   // 0..255
            cp16(&Bs[r * AP + akq], Bb + (long)r * DD + k0 + akq);
        }
        CP_COMMIT();
    };

    issue(0, 0);

    float acc[MT][NT][4] = {};
    int st = 0;
    for (int k0 = 0; k0 < DD; k0 += BK) {
        CP_WAIT0();
        __syncthreads();
        if (k0 + BK < DD) issue(st ^ 1, k0 + BK);
        const float* As = Asm + st * FBM * AP;
        const float* Bs = Bsm + st * NNA * AP;
        #pragma unroll
        for (int ks = 0; ks < BK; ks += 8) {
            uint32_t af[MT][4], bf[NT][2];
            #pragma unroll
            for (int mt = 0; mt < MT; mt++) {
                int m = wm_off + mt * 16 + lr;
                af[mt][0] = __float_as_uint(As[(m    ) * AP + ks + lc    ]);
                af[mt][1] = __float_as_uint(As[(m + 8) * AP + ks + lc    ]);
                af[mt][2] = __float_as_uint(As[(m    ) * AP + ks + lc + 4]);
                af[mt][3] = __float_as_uint(As[(m + 8) * AP + ks + lc + 4]);
            }
            #pragma unroll
            for (int nt = 0; nt < NT; nt++) {
                int n = wn_off + nt * 8 + lr;
                bf[nt][0] = __float_as_uint(Bs[n * AP + ks + lc    ]);
                bf[nt][1] = __float_as_uint(Bs[n * AP + ks + lc + 4]);
            }
            #pragma unroll
            for (int mt = 0; mt < MT; mt++)
                #pragma unroll
                for (int nt = 0; nt < NT; nt++)
                    mma8(acc[mt][nt], af[mt], bf[nt]);
        }
        st ^= 1;
    }

    // stage scores into smem (reusing pipeline space)
    __syncthreads();
    #pragma unroll
    for (int nt = 0; nt < NT; nt++) {
        int col = wn_off + nt * 8 + 2 * lc;
        #pragma unroll
        for (int mt = 0; mt < MT; mt++) {
            int row = wm_off + mt * 16 + lr;
            *(float2*)(&Ss[row * FSP + col])       = make_float2(acc[mt][nt][0], acc[mt][nt][1]);
            *(float2*)(&Ss[(row + 8) * FSP + col]) = make_float2(acc[mt][nt][2], acc[mt][nt][3]);
        }
    }
    __syncthreads();

    // top-8 + softmax + gather: warp w -> rows [w*8, w*8+8)
    for (int rr = 0; rr < 8; rr++) {
        const int row = wid * 8 + rr;
        const float* srow = &Ss[row * FSP];

        float v[8]; int idx[8]; unsigned used = 0;
        #pragma unroll
        for (int q = 0; q < 8; q++) { idx[q] = q*32 + lane; v[q] = srow[q*32 + lane]; }

        float topv[KKK]; int topi[KKK];
        #pragma unroll
        for (int it = 0; it < KKK; it++) {
            float bv = -INFINITY; int bix = 1 << 30;
            #pragma unroll
            for (int q = 0; q < 8; q++) {
                bool ok = !((used >> q) & 1);
                if (ok && (v[q] > bv || (v[q] == bv && idx[q] < bix))) { bv = v[q]; bix = idx[q]; }
            }
            #pragma unroll
            for (int off = 16; off; off >>= 1) {
                float ov = __shfl_down_sync(0xffffffffu, bv, off);
                int   oi = __shfl_down_sync(0xffffffffu, bix, off);
                if (ov > bv || (ov == bv && oi < bix)) { bv = ov; bix = oi; }
            }
            bv  = __shfl_sync(0xffffffffu, bv, 0);
            bix = __shfl_sync(0xffffffffu, bix, 0);
            topv[it] = bv; topi[it] = bix;
            #pragma unroll
            for (int q = 0; q < 8; q++) if (idx[q] == bix) used |= (1u << q);
        }

        float e[KKK]; float s = 0.f;
        #pragma unroll
        for (int it = 0; it < KKK; it++) { e[it] = expf(topv[it] - topv[0]); s += e[it]; }
        const float inv = 1.f / s;

        float a0 = 0.f, a1 = 0.f;
        #pragma unroll
        for (int it = 0; it < KKK; it++) {
            const float* mrow = g_msgs + ((long)b * NNA + topi[it]) * MSGD;
            float g = e[it] * inv;
            a0 += g * mrow[lane];
            a1 += g * mrow[lane + 32];
        }
        const long orow = (long)b * NNA + bi + row;
        g_agg[orow*MSGD + lane]      = to_tf32(a0);
        g_agg[orow*MSGD + lane + 32] = to_tf32(a1);
    }
}

// ============================================================
extern "C" void kernel_launch(void* const* d_in, const int* in_sizes, int n_in,
                              void* d_out, int out_size) {
    const float* obs  = (const float*)d_in[0];
    const float* W1   = (const float*)d_in[1];
    const float* b1   = (const float*)d_in[2];
    const float* W2   = (const float*)d_in[3];
    const float* b2   = (const float*)d_in[4];
    const float* Wc   = (const float*)d_in[5];
    const float* bc   = (const float*)d_in[6];
    const float* Wd   = (const float*)d_in[7];
    const float* bd   = (const float*)d_in[8];
    const float* Wbil = (const float*)d_in[9];
    const float* Wr1  = (const float*)d_in[11];
    const float* br1  = (const float*)d_in[12];
    const float* Wr2  = (const float*)d_in[13];
    const float* br2  = (const float*)d_in[14];
    float* out = (float*)d_out;

    float* obst;   cudaGetSymbolAddress((void**)&obst,   g_obst);
    float* W1t;    cudaGetSymbolAddress((void**)&W1t,    g_W1t);
    float* Wbilt;  cudaGetSymbolAddress((void**)&Wbilt,  g_Wbilt);
    float* Wr1t;   cudaGetSymbolAddress((void**)&Wr1t,   g_Wr1t);
    float* Wr2t;   cudaGetSymbolAddress((void**)&Wr2t,   g_Wr2t);
    float* h;      cudaGetSymbolAddress((void**)&h,      g_h);
    float* msgs;   cudaGetSymbolAddress((void**)&msgs,   g_msgs);
    float* tmp;    cudaGetSymbolAddress((void**)&tmp,    g_tmp);
    float* agg;    cudaGetSymbolAddress((void**)&agg,    g_agg);
    float* r;      cudaGetSymbolAddress((void**)&r,      g_r);
    float* W2p;    cudaGetSymbolAddress((void**)&W2p,    g_W2p);
    float* b2p;    cudaGetSymbolAddress((void**)&b2p,    g_b2p);

    // dynamic smem sizes
    const int SM128 = (3*BM*AP + 3*BK*(128+8)) * 4;           // 56832
    const int SM64  = (3*BM*AP + 3*BK*(64+8))  * 4;           // 44544
    const int SMF   = (FBM*FSP) * 4;                          // 66560 (>= pipeline 51200)

    static bool attr_done = false;
    if (!attr_done) {
        cudaFuncSetAttribute(mma_nn<128,2,4,true,true,true>,   cudaFuncAttributeMaxDynamicSharedMemorySize, SM128);
        cudaFuncSetAttribute(mma_nn<128,2,4,false,false,true>, cudaFuncAttributeMaxDynamicSharedMemorySize, SM128);
        cudaFuncSetAttribute(mma_nn<128,2,4,false,true,false>, cudaFuncAttributeMaxDynamicSharedMemorySize, SM128);
        cudaFuncSetAttribute(mma_nn<64,4,2,false,true,false>,  cudaFuncAttributeMaxDynamicSharedMemorySize, SM64);
        cudaFuncSetAttribute(fused_scores_topk,                cudaFuncAttributeMaxDynamicSharedMemorySize, SMF);
        attr_done = true;
    }

    // prologue: tf32-round obs + weights, compose W2'
    cvt_kernel<<<(BNT*DD/4 + 255)/256, 256>>>(obs, obst, BNT*DD/4);
    cvt_weights<<<((DD+MSGD)*H2D/4 + 255)/256, 256>>>(W1, Wbil, Wr1, Wr2);
    prep_kernel<<<1, 128>>>(W2, b2, Wc, bc, Wd, bd);

    // h = relu(obst @ W1t + b1), tf32-rounded out
    mma_nn<128, 2, 4, true, true, true><<<dim3(1, BNT/BM), 256, SM128>>>(
        obst, DD, obst, DD, DD, W1t, H1D, h, H1D, DD, b1);

    // msgs = h @ W2p + b2p (fp32 out, consumed by fp32 gather)
    mma_nn<64, 4, 2, false, true, false><<<dim3(1, BNT/BM), 256, SM64>>>(
        h, H1D, h, H1D, H1D, W2p, MSGD, msgs, MSGD, H1D, b2p);

    // tmp = obst @ Wbilt, tf32-rounded out
    mma_nn<128, 2, 4, false, false, true><<<dim3(2, BNT/BM), 256, SM128>>>(
        obst, DD, obst, DD, DD, Wbilt, DD, tmp, DD, DD, nullptr);

    // fused: scores -> top-8 -> softmax -> gather -> agg (tf32-rounded)
    fused_scores_topk<<<dim3(NNA/FBM, BB), 256, SMF>>>(tmp, obst);

    // r = relu([obst,agg] @ Wr1t + br1), K=320, tf32-rounded out
    mma_nn<128, 2, 4, true, true, true><<<dim3(2, BNT/BM), 256, SM128>>>(
        obst, DD, agg, MSGD, DD, Wr1t, H2D, r, H2D, DD + MSGD, br1);

    // out = r @ Wr2t + br2 (fp32 out)
    mma_nn<128, 2, 4, false, true, false><<<dim3(2, BNT/BM), 256, SM128>>>(
        r, H2D, r, H2D, H2D, Wr2t, DD, out, DD, H2D, br2);
}

// round 8
// speedup vs baseline: 1.1289x; 1.1289x over previous
#include <cuda_runtime.h>
#include <math.h>
#include <stdint.h>

// Problem dims
#define BB    128
#define NNA   256
#define DD    256
#define MSGD  64
#define CDD   32
#define KKK   8
#define H1D   128
#define H2D   256
#define BNT   (BB*NNA)   // 32768

// -------- device scratch --------
__device__ float g_W2p[H1D*MSGD];
__device__ float g_b2p[MSGD];
__device__ float g_obst[(long)BNT*DD];      // tf32-rounded obs
__device__ float g_W1t [DD*H1D];
__device__ float g_Wbilt[DD*DD];
__device__ float g_Wr1t[(DD+MSGD)*H2D];
__device__ float g_Wr2t[H2D*DD];
__device__ float g_h   [(long)BNT*H1D];
__device__ float g_msgs[(long)BNT*MSGD];
__device__ float g_tmp [(long)BNT*DD];
__device__ float g_scores[(long)BB*NNA*NNA];
__device__ float g_agg [(long)BNT*MSGD];
__device__ float g_r   [(long)BNT*H2D];

// ============================================================
// helpers
// ============================================================
__device__ __forceinline__ float to_tf32(float x) {
    uint32_t u;
    asm("cvt.rna.tf32.f32 %0, %1;" : "=r"(u) : "f"(x));
    return __uint_as_float(u);
}

__device__ __forceinline__ void mma8(float* c, const uint32_t* a, const uint32_t* b) {
    asm volatile(
        "mma.sync.aligned.m16n8k8.row.col.f32.tf32.tf32.f32 "
        "{%0,%1,%2,%3}, {%4,%5,%6,%7}, {%8,%9}, {%0,%1,%2,%3};"
        : "+f"(c[0]), "+f"(c[1]), "+f"(c[2]), "+f"(c[3])
        : "r"(a[0]), "r"(a[1]), "r"(a[2]), "r"(a[3]), "r"(b[0]), "r"(b[1]));
}

__device__ __forceinline__ void cp16(void* smem_dst, const void* gmem_src) {
    uint32_t s = (uint32_t)__cvta_generic_to_shared(smem_dst);
    asm volatile("cp.async.cg.shared.global [%0], [%1], 16;" :: "r"(s), "l"(gmem_src));
}
#define CP_COMMIT() asm volatile("cp.async.commit_group;")
#define CP_WAIT0()  asm volatile("cp.async.wait_group 0;")
#define CP_WAIT1()  asm volatile("cp.async.wait_group 1;")

// ============================================================
// conversion kernels (fp32 -> tf32-rounded fp32)
// ============================================================
__global__ void cvt_kernel(const float* __restrict__ src, float* __restrict__ dst, int n4) {
    int i = blockIdx.x * blockDim.x + threadIdx.x;
    if (i < n4) {
        float4 v = ((const float4*)src)[i];
        ((float4*)dst)[i] = make_float4(to_tf32(v.x), to_tf32(v.y), to_tf32(v.z), to_tf32(v.w));
    }
}

__global__ void cvt_weights(const float* __restrict__ W1, const float* __restrict__ Wbil,
                            const float* __restrict__ Wr1, const float* __restrict__ Wr2) {
    int i = blockIdx.x * blockDim.x + threadIdx.x;
    if (i < DD*H1D/4) {
        float4 v = ((const float4*)W1)[i];
        ((float4*)g_W1t)[i] = make_float4(to_tf32(v.x), to_tf32(v.y), to_tf32(v.z), to_tf32(v.w));
    }
    if (i < DD*DD/4) {
        float4 v = ((const float4*)Wbil)[i];
        ((float4*)g_Wbilt)[i] = make_float4(to_tf32(v.x), to_tf32(v.y), to_tf32(v.z), to_tf32(v.w));
    }
    if (i < (DD+MSGD)*H2D/4) {
        float4 v = ((const float4*)Wr1)[i];
        ((float4*)g_Wr1t)[i] = make_float4(to_tf32(v.x), to_tf32(v.y), to_tf32(v.z), to_tf32(v.w));
    }
    if (i < H2D*DD/4) {
        float4 v = ((const float4*)Wr2)[i];
        ((float4*)g_Wr2t)[i] = make_float4(to_tf32(v.x), to_tf32(v.y), to_tf32(v.z), to_tf32(v.w));
    }
}

// ============================================================
// 0) Compose W2' = W2@Wc@Wd (tf32-rounded), b2' composed (fp32)
// ============================================================
__global__ void prep_kernel(const float* __restrict__ W2, const float* __restrict__ b2,
                            const float* __restrict__ Wc, const float* __restrict__ bc,
                            const float* __restrict__ Wd, const float* __restrict__ bd) {
    __shared__ float bbuf[CDD];
    int t = threadIdx.x; // 128 threads
    float T[CDD];
    #pragma unroll
    for (int c = 0; c < CDD; c++) T[c] = 0.f;
    for (int m = 0; m < MSGD; m++) {
        float w = W2[t*MSGD + m];
        #pragma unroll
        for (int c = 0; c < CDD; c++) T[c] += w * Wc[m*CDD + c];
    }
    for (int mm = 0; mm < MSGD; mm++) {
        float acc = 0.f;
        #pragma unroll
        for (int c = 0; c < CDD; c++) acc += T[c] * Wd[c*MSGD + mm];
        g_W2p[t*MSGD + mm] = to_tf32(acc);
    }
    if (t < CDD) {
        float acc = bc[t];
        for (int m = 0; m < MSGD; m++) acc += b2[m] * Wc[m*CDD + t];
        bbuf[t] = acc;
    }
    __syncthreads();
    if (t < MSGD) {
        float acc = bd[t];
        #pragma unroll
        for (int c = 0; c < CDD; c++) acc += bbuf[c] * Wd[c*MSGD + t];
        g_b2p[t] = acc;
    }
}

// ============================================================
// core tiles: BM=128, BK=32, 3-stage cp.async, warp frag math
// ============================================================
#define BM  128
#define BK  32
#define AP  36   // A smem pitch ([m][k]) -> frag bank = lane (conflict-free)

// ---- generic NN GEMM ----
template<int BNt, int WM, int WN, bool RELU, bool BIASV, bool CVTOUT>
__global__ __launch_bounds__(256, 2) void mma_nn(
    const float* __restrict__ A,  int lda,
    const float* __restrict__ A2, int lda2, int splitK,
    const float* __restrict__ Bw, int ldb,
    float* __restrict__ C, int ldc, int Kdim,
    const float* __restrict__ bias)
{
    static_assert(WM * WN == 8, "");
    constexpr int WTM = BM / WM, WTN = BNt / WN;
    constexpr int MT = WTM / 16, NT = WTN / 8;
    constexpr int BP = BNt + 8;
    constexpr int BCNT = (BK * BNt) / (4 * 256);

    extern __shared__ float sm[];
    float* Asm = sm;                    // [3][BM][AP]
    float* Bsm = sm + 3 * BM * AP;      // [3][BK][BP]

    const int tid  = threadIdx.x;
    const int lane = tid & 31, wid = tid >> 5;
    const int lr = lane >> 2, lc = lane & 3;
    const int wm_off = (wid % WM) * WTM;
    const int wn_off = (wid / WM) * WTN;
    const long bm = (long)blockIdx.y * BM;
    const int  bn = blockIdx.x * BNt;

    auto issue = [&](int st, int k0) {
        float* As = Asm + st * BM * AP;
        float* Bs = Bsm + st * BK * BP;
        #pragma unroll
        for (int i = 0; i < 4; i++) {
            int idx = tid + i * 256;
            int r = idx >> 3, kq = (idx & 7) * 4;
            int k = k0 + kq;
            const float* src = (k < splitK)
                ? (A  + (bm + r) * (long)lda  + k)
                : (A2 + (bm + r) * (long)lda2 + (k - splitK));
            cp16(&As[r * AP + kq], src);
        }
        #pragma unroll
        for (int i = 0; i < BCNT; i++) {
            int idx = tid + i * 256;
            int kk = idx / (BNt / 4), c4 = (idx % (BNt / 4)) * 4;
            cp16(&Bs[kk * BP + c4], Bw + (long)(k0 + kk) * ldb + bn + c4);
        }
        CP_COMMIT();
    };

    issue(0, 0);
    if (BK < Kdim) issue(1, BK);

    float acc[MT][NT][4] = {};
    int st = 0;
    for (int k0 = 0; k0 < Kdim; k0 += BK) {
        if (k0 + BK < Kdim) { CP_WAIT1(); } else { CP_WAIT0(); }
        __syncthreads();
        if (k0 + 2 * BK < Kdim) issue((st + 2) % 3, k0 + 2 * BK);
        const float* As = Asm + st * BM * AP;
        const float* Bs = Bsm + st * BK * BP;
        #pragma unroll
        for (int ks = 0; ks < BK; ks += 8) {
            uint32_t af[MT][4], bf[NT][2];
            #pragma unroll
            for (int mt = 0; mt < MT; mt++) {
                int m = wm_off + mt * 16 + lr;
                af[mt][0] = __float_as_uint(As[(m    ) * AP + ks + lc    ]);
                af[mt][1] = __float_as_uint(As[(m + 8) * AP + ks + lc    ]);
                af[mt][2] = __float_as_uint(As[(m    ) * AP + ks + lc + 4]);
                af[mt][3] = __float_as_uint(As[(m + 8) * AP + ks + lc + 4]);
            }
            #pragma unroll
            for (int nt = 0; nt < NT; nt++) {
                int n = wn_off + nt * 8 + lr;
                bf[nt][0] = __float_as_uint(Bs[(ks + lc    ) * BP + n]);
                bf[nt][1] = __float_as_uint(Bs[(ks + lc + 4) * BP + n]);
            }
            #pragma unroll
            for (int mt = 0; mt < MT; mt++)
                #pragma unroll
                for (int nt = 0; nt < NT; nt++)
                    mma8(acc[mt][nt], af[mt], bf[nt]);
        }
        st = (st + 1) % 3;
    }

    #pragma unroll
    for (int nt = 0; nt < NT; nt++) {
        int col = bn + wn_off + nt * 8 + 2 * lc;
        float b0 = 0.f, b1 = 0.f;
        if (BIASV) { b0 = bias[col]; b1 = bias[col + 1]; }
        #pragma unroll
        for (int mt = 0; mt < MT; mt++) {
            long row = bm + wm_off + mt * 16 + lr;
            float v0 = acc[mt][nt][0] + b0, v1 = acc[mt][nt][1] + b1;
            float v2 = acc[mt][nt][2] + b0, v3 = acc[mt][nt][3] + b1;
            if (RELU) {
                v0 = fmaxf(v0, 0.f); v1 = fmaxf(v1, 0.f);
                v2 = fmaxf(v2, 0.f); v3 = fmaxf(v3, 0.f);
            }
            if (CVTOUT) {
                v0 = to_tf32(v0); v1 = to_tf32(v1);
                v2 = to_tf32(v2); v3 = to_tf32(v3);
            }
            *(float2*)(C + row * ldc + col)       = make_float2(v0, v1);
            *(float2*)(C + (row + 8) * ldc + col) = make_float2(v2, v3);
        }
    }
}

// ---- merged h + tmp GEMM over virtual B = [W1t | Wbilt] (N=384) ----
//   block 0:   h  = relu(obst @ W1t + b1), tf32-rounded out  (ldc 128)
//   block 1,2: tmp = obst @ Wbilt, tf32-rounded out          (ldc 256)
__global__ __launch_bounds__(256, 2) void mma_htmp(
    const float* __restrict__ Aobs,
    const float* __restrict__ b1)
{
    constexpr int WM = 2, WN = 4, WTM = 64, WTN = 32, MT = 4, NT = 4;
    constexpr int BNt = 128, BP = BNt + 8;

    extern __shared__ float sm[];
    float* Asm = sm;
    float* Bsm = sm + 3 * BM * AP;

    const int tid  = threadIdx.x;
    const int lane = tid & 31, wid = tid >> 5;
    const int lr = lane >> 2, lc = lane & 3;
    const int wm_off = (wid % WM) * WTM;
    const int wn_off = (wid / WM) * WTN;
    const long bm = (long)blockIdx.y * BM;
    const bool is_h = (blockIdx.x == 0);
    const float* Bw  = is_h ? g_W1t : g_Wbilt;
    const int    ldb = is_h ? H1D : DD;
    const int    bcol = is_h ? 0 : (blockIdx.x - 1) * BNt;

    auto issue = [&](int st, int k0) {
        float* As = Asm + st * BM * AP;
        float* Bs = Bsm + st * BK * BP;
        #pragma unroll
        for (int i = 0; i < 4; i++) {
            int idx = tid + i * 256;
            int r = idx >> 3, kq = (idx & 7) * 4;
            cp16(&As[r * AP + kq], Aobs + (bm + r) * (long)DD + k0 + kq);
        }
        #pragma unroll
        for (int i = 0; i < 4; i++) {
            int idx = tid + i * 256;
            int kk = idx >> 5, c4 = (idx & 31) * 4;
            cp16(&Bs[kk * BP + c4], Bw + (long)(k0 + kk) * ldb + bcol + c4);
        }
        CP_COMMIT();
    };

    issue(0, 0); issue(1, BK);

    float acc[MT][NT][4] = {};
    int st = 0;
    for (int k0 = 0; k0 < DD; k0 += BK) {
        if (k0 + BK < DD) { CP_WAIT1(); } else { CP_WAIT0(); }
        __syncthreads();
        if (k0 + 2 * BK < DD) issue((st + 2) % 3, k0 + 2 * BK);
        const float* As = Asm + st * BM * AP;
        const float* Bs = Bsm + st * BK * BP;
        #pragma unroll
        for (int ks = 0; ks < BK; ks += 8) {
            uint32_t af[MT][4], bf[NT][2];
            #pragma unroll
            for (int mt = 0; mt < MT; mt++) {
                int m = wm_off + mt * 16 + lr;
                af[mt][0] = __float_as_uint(As[(m    ) * AP + ks + lc    ]);
                af[mt][1] = __float_as_uint(As[(m + 8) * AP + ks + lc    ]);
                af[mt][2] = __float_as_uint(As[(m    ) * AP + ks + lc + 4]);
                af[mt][3] = __float_as_uint(As[(m + 8) * AP + ks + lc + 4]);
            }
            #pragma unroll
            for (int nt = 0; nt < NT; nt++) {
                int n = wn_off + nt * 8 + lr;
                bf[nt][0] = __float_as_uint(Bs[(ks + lc    ) * BP + n]);
                bf[nt][1] = __float_as_uint(Bs[(ks + lc + 4) * BP + n]);
            }
            #pragma unroll
            for (int mt = 0; mt < MT; mt++)
                #pragma unroll
                for (int nt = 0; nt < NT; nt++)
                    mma8(acc[mt][nt], af[mt], bf[nt]);
        }
        st = (st + 1) % 3;
    }

    float* C = is_h ? g_h : g_tmp;
    const int ldc = is_h ? H1D : DD;
    #pragma unroll
    for (int nt = 0; nt < NT; nt++) {
        int lcol = wn_off + nt * 8 + 2 * lc;
        int col = bcol + lcol;
        float b0 = 0.f, b1v = 0.f;
        if (is_h) { b0 = b1[col]; b1v = b1[col + 1]; }
        #pragma unroll
        for (int mt = 0; mt < MT; mt++) {
            long row = bm + wm_off + mt * 16 + lr;
            float v0 = acc[mt][nt][0] + b0, v1 = acc[mt][nt][1] + b1v;
            float v2 = acc[mt][nt][2] + b0, v3 = acc[mt][nt][3] + b1v;
            if (is_h) {
                v0 = fmaxf(v0, 0.f); v1 = fmaxf(v1, 0.f);
                v2 = fmaxf(v2, 0.f); v3 = fmaxf(v3, 0.f);
            }
            v0 = to_tf32(v0); v1 = to_tf32(v1);
            v2 = to_tf32(v2); v3 = to_tf32(v3);
            *(float2*)(C + row * ldc + col)       = make_float2(v0, v1);
            *(float2*)(C + (row + 8) * ldc + col) = make_float2(v2, v3);
        }
    }
}

// ---- batched NT GEMM: scores[b] = tmp[b] @ obst[b]^T + bbil ----
__global__ __launch_bounds__(256, 2) void mma_nt(
    const float* __restrict__ A, const float* __restrict__ Bm,
    float* __restrict__ C, const float* __restrict__ bbil)
{
    constexpr int WM = 2, WTM = 64, WTN = 32, MT = 4, NT = 4;
    extern __shared__ float sm[];
    float* Asm = sm;                    // [3][128][AP]
    float* Bsm = sm + 3 * BM * AP;      // [3][128][AP]  ([n][k])

    const int tid  = threadIdx.x;
    const int lane = tid & 31, wid = tid >> 5;
    const int lr = lane >> 2, lc = lane & 3;
    const int wm_off = (wid % WM) * WTM;
    const int wn_off = (wid / WM) * WTN;
    const int b = blockIdx.z;
    const float* Ab = A  + (long)b * NNA * DD;
    const float* Bb = Bm + (long)b * NNA * DD;
    float* Cb = C + (long)b * NNA * NNA;
    const int bi = blockIdx.y * BM;
    const int bj = blockIdx.x * BM;

    auto issue = [&](int st, int k0) {
        float* As = Asm + st * BM * AP;
        float* Bs = Bsm + st * BM * AP;
        #pragma unroll
        for (int i = 0; i < 4; i++) {
            int idx = tid + i * 256;
            int r = idx >> 3, kq = (idx & 7) * 4;
            cp16(&As[r * AP + kq], Ab + (long)(bi + r) * DD + k0 + kq);
            cp16(&Bs[r * AP + kq], Bb + (long)(bj + r) * DD + k0 + kq);
        }
        CP_COMMIT();
    };

    issue(0, 0); issue(1, BK);

    float acc[MT][NT][4] = {};
    int st = 0;
    for (int k0 = 0; k0 < DD; k0 += BK) {
        if (k0 + BK < DD) { CP_WAIT1(); } else { CP_WAIT0(); }
        __syncthreads();
        if (k0 + 2 * BK < DD) issue((st + 2) % 3, k0 + 2 * BK);
        const float* As = Asm + st * BM * AP;
        const float* Bs = Bsm + st * BM * AP;
        #pragma unroll
        for (int ks = 0; ks < BK; ks += 8) {
            uint32_t af[MT][4], bf[NT][2];
            #pragma unroll
            for (int mt = 0; mt < MT; mt++) {
                int m = wm_off + mt * 16 + lr;
                af[mt][0] = __float_as_uint(As[(m    ) * AP + ks + lc    ]);
                af[mt][1] = __float_as_uint(As[(m + 8) * AP + ks + lc    ]);
                af[mt][2] = __float_as_uint(As[(m    ) * AP + ks + lc + 4]);
                af[mt][3] = __float_as_uint(As[(m + 8) * AP + ks + lc + 4]);
            }
            #pragma unroll
            for (int nt = 0; nt < NT; nt++) {
                int n = wn_off + nt * 8 + lr;
                bf[nt][0] = __float_as_uint(Bs[n * AP + ks + lc    ]);
                bf[nt][1] = __float_as_uint(Bs[n * AP + ks + lc + 4]);
            }
            #pragma unroll
            for (int mt = 0; mt < MT; mt++)
                #pragma unroll
                for (int nt = 0; nt < NT; nt++)
                    mma8(acc[mt][nt], af[mt], bf[nt]);
        }
        st = (st + 1) % 3;
    }

    const float bv = *bbil;
    #pragma unroll
    for (int nt = 0; nt < NT; nt++) {
        int col = bj + wn_off + nt * 8 + 2 * lc;
        #pragma unroll
        for (int mt = 0; mt < MT; mt++) {
            int row = bi + wm_off + mt * 16 + lr;
            *(float2*)(Cb + (long)row * NNA + col) =
                make_float2(acc[mt][nt][0] + bv, acc[mt][nt][1] + bv);
            *(float2*)(Cb + (long)(row + 8) * NNA + col) =
                make_float2(acc[mt][nt][2] + bv, acc[mt][nt][3] + bv);
        }
    }
}

// ============================================================
// top-8 + softmax + weighted gather of msgs -> agg
// ============================================================
__global__ __launch_bounds__(256) void topk_agg_kernel() {
    const int warp = threadIdx.x >> 5, lane = threadIdx.x & 31;
    const long row = (long)blockIdx.x * 8 + warp;
    const int b = (int)(row >> 8);
    const float* srow = g_scores + row * NNA;

    float v[8]; int idx[8]; unsigned used = 0;
    #pragma unroll
    for (int q = 0; q < 8; q++) { idx[q] = q*32 + lane; v[q] = srow[q*32 + lane]; }

    float topv[KKK]; int topi[KKK];
    #pragma unroll
    for (int it = 0; it < KKK; it++) {
        float bv = -INFINITY; int bi = 1 << 30;
        #pragma unroll
        for (int q = 0; q < 8; q++) {
            bool ok = !((used >> q) & 1);
            if (ok && (v[q] > bv || (v[q] == bv && idx[q] < bi))) { bv = v[q]; bi = idx[q]; }
        }
        #pragma unroll
        for (int off = 16; off; off >>= 1) {
            float ov = __shfl_down_sync(0xffffffffu, bv, off);
            int   oi = __shfl_down_sync(0xffffffffu, bi, off);
            if (ov > bv || (ov == bv && oi < bi)) { bv = ov; bi = oi; }
        }
        bv = __shfl_sync(0xffffffffu, bv, 0);
        bi = __shfl_sync(0xffffffffu, bi, 0);
        topv[it] = bv; topi[it] = bi;
        #pragma unroll
        for (int q = 0; q < 8; q++) if (idx[q] == bi) used |= (1u << q);
    }

    float e[KKK]; float s = 0.f;
    #pragma unroll
    for (int it = 0; it < KKK; it++) { e[it] = expf(topv[it] - topv[0]); s += e[it]; }
    const float inv = 1.f / s;

    float a0 = 0.f, a1 = 0.f;
    #pragma unroll
    for (int it = 0; it < KKK; it++) {
        const float* mrow = g_msgs + ((long)b * NNA + topi[it]) * MSGD;
        float g = e[it] * inv;
        a0 += g * mrow[lane];
        a1 += g * mrow[lane + 32];
    }
    g_agg[row*MSGD + lane]      = to_tf32(a0);
    g_agg[row*MSGD + lane + 32] = to_tf32(a1);
}

// ============================================================
extern "C" void kernel_launch(void* const* d_in, const int* in_sizes, int n_in,
                              void* d_out, int out_size) {
    const float* obs  = (const float*)d_in[0];
    const float* W1   = (const float*)d_in[1];
    const float* b1   = (const float*)d_in[2];
    const float* W2   = (const float*)d_in[3];
    const float* b2   = (const float*)d_in[4];
    const float* Wc   = (const float*)d_in[5];
    const float* bc   = (const float*)d_in[6];
    const float* Wd   = (const float*)d_in[7];
    const float* bd   = (const float*)d_in[8];
    const float* Wbil = (const float*)d_in[9];
    const float* bbil = (const float*)d_in[10];
    const float* Wr1  = (const float*)d_in[11];
    const float* br1  = (const float*)d_in[12];
    const float* Wr2  = (const float*)d_in[13];
    const float* br2  = (const float*)d_in[14];
    float* out = (float*)d_out;

    float* obst;   cudaGetSymbolAddress((void**)&obst,   g_obst);
    float* h;      cudaGetSymbolAddress((void**)&h,      g_h);
    float* msgs;   cudaGetSymbolAddress((void**)&msgs,   g_msgs);
    float* tmp;    cudaGetSymbolAddress((void**)&tmp,    g_tmp);
    float* scores; cudaGetSymbolAddress((void**)&scores, g_scores);
    float* agg;    cudaGetSymbolAddress((void**)&agg,    g_agg);
    float* r;      cudaGetSymbolAddress((void**)&r,      g_r);
    float* W2p;    cudaGetSymbolAddress((void**)&W2p,    g_W2p);
    float* b2p;    cudaGetSymbolAddress((void**)&b2p,    g_b2p);
    float* Wr1t;   cudaGetSymbolAddress((void**)&Wr1t,   g_Wr1t);
    float* Wr2t;   cudaGetSymbolAddress((void**)&Wr2t,   g_Wr2t);

    // dynamic smem sizes (BK=32, 3 stages)
    const int SM128 = (3*BM*AP + 3*BK*(128+8)) * 4;   // 107,520
    const int SM64  = (3*BM*AP + 3*BK*(64+8))  * 4;   //  82,944
    const int SMNT  = (3*BM*AP * 2) * 4;              // 110,592

    static bool attr_done = false;
    if (!attr_done) {
        cudaFuncSetAttribute(mma_nn<128,2,4,true,true,true>,   cudaFuncAttributeMaxDynamicSharedMemorySize, SM128);
        cudaFuncSetAttribute(mma_nn<128,2,4,false,true,false>, cudaFuncAttributeMaxDynamicSharedMemorySize, SM128);
        cudaFuncSetAttribute(mma_nn<64,4,2,false,true,false>,  cudaFuncAttributeMaxDynamicSharedMemorySize, SM64);
        cudaFuncSetAttribute(mma_htmp,                         cudaFuncAttributeMaxDynamicSharedMemorySize, SM128);
        cudaFuncSetAttribute(mma_nt,                           cudaFuncAttributeMaxDynamicSharedMemorySize, SMNT);
        attr_done = true;
    }

    // prologue: tf32-round obs + weights, compose W2'
    cvt_kernel<<<(BNT*DD/4 + 255)/256, 256>>>(obs, obst, BNT*DD/4);
    cvt_weights<<<((DD+MSGD)*H2D/4 + 255)/256, 256>>>(W1, Wbil, Wr1, Wr2);
    prep_kernel<<<1, 128>>>(W2, b2, Wc, bc, Wd, bd);

    // merged: h = relu(obst@W1t+b1) [block 0], tmp = obst@Wbilt [blocks 1,2]
    mma_htmp<<<dim3(3, BNT/BM), 256, SM128>>>(obst, b1);

    // msgs = h @ W2p + b2p (fp32 out)
    mma_nn<64, 4, 2, false, true, false><<<dim3(1, BNT/BM), 256, SM64>>>(
        h, H1D, h, H1D, H1D, W2p, MSGD, msgs, MSGD, H1D, b2p);

    // scores[b] = tmp[b] @ obst[b]^T + bbil
    mma_nt<<<dim3(2, 2, BB), 256, SMNT>>>(tmp, obst, scores, bbil);

    // top-8 + softmax + gather -> agg (tf32-rounded)
    topk_agg_kernel<<<BNT / 8, 256>>>();

    // r = relu([obst,agg] @ Wr1t + br1), K=320, tf32-rounded out
    mma_nn<128, 2, 4, true, true, true><<<dim3(2, BNT/BM), 256, SM128>>>(
        obst, DD, agg, MSGD, DD, Wr1t, H2D, r, H2D, DD + MSGD, br1);

    // out = r @ Wr2t + br2 (fp32 out)
    mma_nn<128, 2, 4, false, true, false><<<dim3(2, BNT/BM), 256, SM128>>>(
        r, H2D, r, H2D, H2D, Wr2t, DD, out, DD, H2D, br2);
}